// round 9
// baseline (speedup 1.0000x reference)
#include <cuda_runtime.h>
#include <cuda_fp16.h>
#include <cuda_bf16.h>

// Problem constants (from reference_code)
#define N_PATHS  10000000
#define MAX_LEN  3
#define N_NODES  100000
#define HIDDEN   128

// fp16 planar projection table: g_t16[l * N_NODES + node], 600 KB total.
__device__ __half g_t16[3 * N_NODES];

// ---------------------------------------------------------------------------
// Kernel 1: proj[l][node] = dot(feature[node], W[l][0]) -> fp16 planar table.
// One warp per FOUR nodes, all 4 feature loads front-batched (MLP=4) so the
// ~600-cycle DRAM latency is overlapped. nf reads are evict-first streaming.
// 100000 % 4 == 0 -> no tail guards.
// ---------------------------------------------------------------------------
__global__ void __launch_bounds__(256)
proj_kernel(const float* __restrict__ nf, const float* __restrict__ W) {
    const int lane   = threadIdx.x & 31;
    const int warpId = (blockIdx.x * blockDim.x + threadIdx.x) >> 5;
    const int n0     = warpId * 4;
    if (n0 >= N_NODES) return;

    // W rows (L1-resident after first block), lane t holds dims [4t, 4t+4)
    const float4 w0 = __ldg(((const float4*)W) + 0  + lane);
    const float4 w1 = __ldg(((const float4*)W) + 32 + lane);
    const float4 w2 = __ldg(((const float4*)W) + 64 + lane);

    // Front-batched feature loads: 4 independent 128B/warp requests in flight
    float4 f[4];
    #pragma unroll
    for (int i = 0; i < 4; i++)
        f[i] = __ldcs(((const float4*)nf) + (size_t)(n0 + i) * 32 + lane);

    #pragma unroll
    for (int i = 0; i < 4; i++) {
        float s0 = f[i].x * w0.x + f[i].y * w0.y + f[i].z * w0.z + f[i].w * w0.w;
        float s1 = f[i].x * w1.x + f[i].y * w1.y + f[i].z * w1.z + f[i].w * w1.w;
        float s2 = f[i].x * w2.x + f[i].y * w2.y + f[i].z * w2.z + f[i].w * w2.w;

        #pragma unroll
        for (int o = 16; o > 0; o >>= 1) {
            s0 += __shfl_xor_sync(0xFFFFFFFFu, s0, o);
            s1 += __shfl_xor_sync(0xFFFFFFFFu, s1, o);
            s2 += __shfl_xor_sync(0xFFFFFFFFu, s2, o);
        }

        if (lane == 0) {
            const int node = n0 + i;
            g_t16[0 * N_NODES + node] = __float2half(s0);
            g_t16[1 * N_NODES + node] = __float2half(s1);
            g_t16[2 * N_NODES + node] = __float2half(s2);
        }
    }
}

// ---------------------------------------------------------------------------
// Kernel 2: gather + masked mean. UNCHANGED from R7 (measured at the L1tex
// wavefront floor: ~1.0 wf/cyc/SM; every perturbation so far regressed).
// ---------------------------------------------------------------------------
__global__ void __launch_bounds__(256)
gather_kernel(const int* __restrict__ paths, float* __restrict__ out) {
    const long long tid = (long long)blockIdx.x * blockDim.x + threadIdx.x;
    if (tid >= (N_PATHS / 4)) return;

    const int4* p4 = ((const int4*)paths) + tid * 3;
    int4 v0 = __ldcs(p4 + 0);
    int4 v1 = __ldcs(p4 + 1);
    int4 v2 = __ldcs(p4 + 2);

    int idx[12] = { v0.x, v0.y, v0.z, v0.w,
                    v1.x, v1.y, v1.z, v1.w,
                    v2.x, v2.y, v2.z, v2.w };

    float4 res;
    float* r = (float*)&res;

    #pragma unroll
    for (int k = 0; k < 4; k++) {
        float s = 0.0f;
        int   cnt = 0;
        #pragma unroll
        for (int l = 0; l < 3; l++) {
            const int p = idx[k * 3 + l];
            if (p >= 0) {                     // predicated LDG + SEL (no branch)
                s += __half2float(g_t16[l * N_NODES + p]);
                cnt++;
            }
        }
        float inv = (cnt == 3) ? (1.0f / 3.0f)
                               : ((cnt == 2) ? 0.5f : 1.0f);
        r[k] = s * inv;
    }

    __stcs(((float4*)out) + tid, res);
}

// ---------------------------------------------------------------------------
// Launch. Inputs identified by element count:
//   30,000,000 -> paths (int32 [10M,3]); 12,800,000 -> node_feature; 384 -> W
// ---------------------------------------------------------------------------
extern "C" void kernel_launch(void* const* d_in, const int* in_sizes, int n_in,
                              void* d_out, int out_size) {
    const void*  paths_raw = nullptr;
    const float* nf        = nullptr;
    const float* W         = nullptr;

    for (int i = 0; i < n_in; i++) {
        if      (in_sizes[i] == N_PATHS * MAX_LEN)  paths_raw = d_in[i];
        else if (in_sizes[i] == N_NODES * HIDDEN)   nf        = (const float*)d_in[i];
        else if (in_sizes[i] == MAX_LEN * HIDDEN)   W         = (const float*)d_in[i];
    }

    float* out = (float*)d_out;

    // proj: one warp per 4 nodes -> 25000 warps -> 3125 blocks of 256
    {
        const int threads = 256;
        const int warps   = N_NODES / 4;                 // 25000
        const int blocks  = (warps * 32 + threads - 1) / threads;
        proj_kernel<<<blocks, threads>>>(nf, W);
    }

    // gather: 2.5M threads, 4 paths each
    {
        const int threads = 256;
        const long long nThreads = N_PATHS / 4;
        const int blocks = (int)((nThreads + threads - 1) / threads);
        gather_kernel<<<blocks, threads>>>((const int*)paths_raw, out);
    }
}